// round 13
// baseline (speedup 1.0000x reference)
#include <cuda_runtime.h>
#include <cuda_fp16.h>
#include <cstdint>
#include <cstddef>

// Problem dims
#define BB   8
#define CC   256
#define CHI  128
#define HH   64
#define WW   64
#define NPIX 4096   // H*W
#define MPOOL 1024  // (H/2)*(W/2)

// ---------------- gmem "smem-image" buffers ----------------
// lane_off(r, c<32) = r*80 + (c>>3)*16 + (c&7)*2
__device__ __align__(128) char g_kimg[(size_t)8 * 32 * 8 * 20480];
__device__ __align__(128) char g_wthimg[8 * 20480];
__device__ __align__(128) char g_wphimg[8 * 20480];
__device__ __align__(128) char g_wgimg[8 * 10240];
__device__ __align__(128) char g_wwimg[8 * 10240];
__device__ __align__(128) char g_pqimg[(size_t)8 * 8 * 8 * 20480];
__device__ __align__(128) char g_pvimg[(size_t)8 * 8 * 8 * 10240];
// pgimg: per (b, mt64) 61440 = [phi_hi 4ch x 64x80 | phi_lo | g 2ch x 128x80]
__device__ __align__(128) char g_pgimg[(size_t)8 * 16 * 61440];
__device__ float g_bns[CC];
__device__ float g_bnt[CC];
__device__ int g_sync[BB * 16];   // per (b, mt64) readiness: 2 = phi+g both done

// ---------------- PTX helpers ----------------
__device__ __forceinline__ uint32_t smem_u32(const void* p) {
    uint32_t a;
    asm("{ .reg .u64 t; cvta.to.shared.u64 t, %1; cvt.u32.u64 %0, t; }" : "=r"(a) : "l"(p));
    return a;
}
__device__ __forceinline__ void cpbulk(uint32_t dst, const void* src, uint32_t bytes,
                                       uint32_t mbar) {
    asm volatile(
        "cp.async.bulk.shared::cluster.global.mbarrier::complete_tx::bytes [%0], [%1], %2, [%3];"
        :: "r"(dst), "l"(src), "r"(bytes), "r"(mbar) : "memory");
}
#define MBAR_INIT(mb, n) \
    asm volatile("mbarrier.init.shared.b64 [%0], %1;" :: "r"(mb), "r"((uint32_t)(n)) : "memory")
#define MBAR_EXPECT(mb, n) \
    asm volatile("mbarrier.arrive.expect_tx.shared.b64 _, [%0], %1;" :: "r"(mb), "r"((uint32_t)(n)) : "memory")

__device__ __forceinline__ void mbar_wait(uint32_t mb, uint32_t parity) {
    uint32_t done;
    asm volatile(
        "{\n\t.reg .pred p;\n\t"
        "mbarrier.try_wait.parity.acquire.cta.shared::cta.b64 p, [%1], %2;\n\t"
        "selp.b32 %0, 1, 0, p;\n\t}"
        : "=r"(done) : "r"(mb), "r"(parity) : "memory");
    if (!done) {
        asm volatile(
            "{\n\t.reg .pred P1;\n\t"
            "W0_%=:\n\t"
            "mbarrier.try_wait.parity.acquire.cta.shared::cta.b64 P1, [%0], %1, 0x989680;\n\t"
            "@P1 bra.uni W1_%=;\n\t"
            "bra.uni W0_%=;\n\t"
            "W1_%=:\n\t}"
            :: "r"(mb), "r"(parity) : "memory");
    }
}
__device__ __forceinline__ void ldsm4(uint32_t& r0, uint32_t& r1, uint32_t& r2, uint32_t& r3,
                                      uint32_t a) {
    asm volatile("ldmatrix.sync.aligned.m8n8.x4.shared.b16 {%0,%1,%2,%3}, [%4];"
                 : "=r"(r0), "=r"(r1), "=r"(r2), "=r"(r3) : "r"(a));
}
__device__ __forceinline__ void mma16816(float* c, const uint32_t* a, const uint32_t* b) {
    asm volatile(
        "mma.sync.aligned.m16n8k16.row.col.f32.f16.f16.f32 "
        "{%0,%1,%2,%3}, {%4,%5,%6,%7}, {%8,%9}, {%0,%1,%2,%3};"
        : "+f"(c[0]), "+f"(c[1]), "+f"(c[2]), "+f"(c[3])
        : "r"(a[0]), "r"(a[1]), "r"(a[2]), "r"(a[3]), "r"(b[0]), "r"(b[1]));
}
__device__ __forceinline__ uint32_t pkh2(float a, float b) {
    __half2 h = __floats2half2_rn(a, b);
    return *(uint32_t*)&h;
}
__device__ __forceinline__ uint32_t lane_off(int r, int c) {
    return (uint32_t)(r * 80 + (c >> 3) * 16 + (c & 7) * 2);
}

// ---------------- 3-stage bulk-fed GEMM body (phi/g projections) ----------------
// EPI 5: phi -> pgimg (col bias, split hi/lo) | 6: g -> pgimg (row bias)
template <int NCH, bool SPLIT, int EPI>
__device__ __forceinline__ void gemm_body(
    const char* __restrict__ Ab, const char* __restrict__ Bb,
    char* smraw, uint32_t mb0, int z, int by, int bx,
    const float* __restrict__ bias, char* __restrict__ outImg, int tid) {
    constexpr uint32_t REG = SPLIT ? 20480 : 10240;
    constexpr uint32_t STAGE = SPLIT ? 40960 : 20480;
    uint32_t sbase = smem_u32(smraw);
    int lane = tid & 31, w = tid >> 5;
    int wm = w >> 2, wn = w & 3;

    if (tid == 0) { MBAR_INIT(mb0, 1); MBAR_INIT(mb0 + 8, 1); MBAR_INIT(mb0 + 16, 1); }
    __syncthreads();

    auto issue = [&](int ch) {
        uint32_t st = sbase + (uint32_t)(ch % 3) * STAGE;
        uint32_t mb = mb0 + (uint32_t)(ch % 3) * 8;
        MBAR_EXPECT(mb, SPLIT ? 40960u : 20480u);
        if (SPLIT) {
            cpbulk(st, Ab + (size_t)ch * REG, 10240, mb);
            cpbulk(st + 20480, Ab + (size_t)ch * REG + 10240, 10240, mb);
            cpbulk(st + 10240, Bb + (size_t)ch * REG, 10240, mb);
            cpbulk(st + 30720, Bb + (size_t)ch * REG + 10240, 10240, mb);
        } else {
            cpbulk(st, Ab + (size_t)ch * REG, 10240, mb);
            cpbulk(st + 10240, Bb + (size_t)ch * REG, 10240, mb);
        }
    };
    if (tid == 0) { issue(0); issue(1); issue(2); }

    float acc[4][4][4];
#pragma unroll
    for (int i = 0; i < 4; i++)
#pragma unroll
        for (int j = 0; j < 4; j++)
#pragma unroll
            for (int e = 0; e < 4; e++) acc[i][j][e] = 0.f;

    for (int ch = 0; ch < NCH; ch++) {
        mbar_wait(mb0 + (uint32_t)(ch % 3) * 8, (uint32_t)((ch / 3) & 1));
        uint32_t sa = sbase + (uint32_t)(ch % 3) * STAGE;
        uint32_t sb = sa + 10240;
#pragma unroll
        for (int k16 = 0; k16 < 2; k16++) {
            uint32_t a[4][4], b[4][2];
            uint32_t coff = (uint32_t)(k16 * 32 + (lane >> 4) * 16);
#pragma unroll
            for (int mi = 0; mi < 4; mi++) {
                uint32_t ad = sa + (uint32_t)(wm * 64 + mi * 16 + (lane & 15)) * 80 + coff;
                ldsm4(a[mi][0], a[mi][1], a[mi][2], a[mi][3], ad);
            }
#pragma unroll
            for (int nh = 0; nh < 2; nh++) {
                uint32_t bd = sb + (uint32_t)(wn * 32 + nh * 16 + (lane & 15)) * 80 + coff;
                uint32_t r0, r1, r2, r3;
                ldsm4(r0, r1, r2, r3, bd);
                b[nh * 2 + 0][0] = r0; b[nh * 2 + 0][1] = r2;
                b[nh * 2 + 1][0] = r1; b[nh * 2 + 1][1] = r3;
            }
#pragma unroll
            for (int mi = 0; mi < 4; mi++)
#pragma unroll
                for (int ni = 0; ni < 4; ni++) mma16816(acc[mi][ni], a[mi], b[ni]);
            if (SPLIT) {
                uint32_t al[4][4], bl[4][2];
#pragma unroll
                for (int mi = 0; mi < 4; mi++) {
                    uint32_t ad = sa + 20480 + (uint32_t)(wm * 64 + mi * 16 + (lane & 15)) * 80 + coff;
                    ldsm4(al[mi][0], al[mi][1], al[mi][2], al[mi][3], ad);
                }
#pragma unroll
                for (int nh = 0; nh < 2; nh++) {
                    uint32_t bd = sa + 30720 + (uint32_t)(wn * 32 + nh * 16 + (lane & 15)) * 80 + coff;
                    uint32_t r0, r1, r2, r3;
                    ldsm4(r0, r1, r2, r3, bd);
                    bl[nh * 2 + 0][0] = r0; bl[nh * 2 + 0][1] = r2;
                    bl[nh * 2 + 1][0] = r1; bl[nh * 2 + 1][1] = r3;
                }
#pragma unroll
                for (int mi = 0; mi < 4; mi++)
#pragma unroll
                    for (int ni = 0; ni < 4; ni++) {
                        mma16816(acc[mi][ni], a[mi], bl[ni]);
                        mma16816(acc[mi][ni], al[mi], b[ni]);
                    }
            }
        }
        __syncthreads();
        if (tid == 0 && ch + 3 < NCH) issue(ch + 3);
    }

    int r = lane >> 2, cp2 = (lane & 3) * 2;
    int row0 = by * 128 + wm * 64;
    int col0 = bx * 128 + wn * 32;
#pragma unroll
    for (int mi = 0; mi < 4; mi++) {
#pragma unroll
        for (int h = 0; h < 2; h++) {
            int row = row0 + mi * 16 + h * 8 + r;
            float t = (EPI == 6) ? bias[row] : 0.f;
#pragma unroll
            for (int ni = 0; ni < 4; ni++) {
                int col = col0 + ni * 8 + cp2;
                float v0 = acc[mi][ni][h * 2 + 0];
                float v1 = acc[mi][ni][h * 2 + 1];
                if (EPI == 5) {
                    v0 += bias[col]; v1 += bias[col + 1];
                    __half h0 = __float2half_rn(v0), h1 = __float2half_rn(v1);
                    uint32_t hi = ((uint32_t)*(uint16_t*)&h1 << 16) | *(uint16_t*)&h0;
                    uint32_t lo = pkh2(v0 - __half2float(h0), v1 - __half2float(h1));
                    char* base = outImg + (size_t)(z * 16 + (row >> 6)) * 61440;
                    uint32_t off = (uint32_t)(col >> 5) * 5120 + lane_off(row & 63, col & 31);
                    *(uint32_t*)(base + off) = hi;
                    *(uint32_t*)(base + off + 20480) = lo;
                } else {
                    uint32_t hv = pkh2(v0 + t, v1 + t);
                    char* base = outImg + (size_t)(z * 16 + (col >> 6)) * 61440 + 40960;
                    uint32_t off = (uint32_t)((col >> 5) & 1) * 10240 + lane_off(row, col & 31);
                    *(uint32_t*)(base + off) = hv;
                }
            }
        }
    }
}

// ---------------- merged mid+flash kernel ----------------
// blocks 0..127: mid role (phi 0-63, g 64-127), signal g_sync flags.
// blocks 128..383: flash role, spin on flags before issuing pgimg tiles.
__global__ void __launch_bounds__(256, 1) midflash_kernel(
    const float* __restrict__ bph, const float* __restrict__ bg,
    const float* __restrict__ bth, const float* __restrict__ vres,
    float* __restrict__ out) {
    extern __shared__ char sm[];
    __shared__ __align__(8) uint64_t s_mbar[3];
    uint32_t sbase = smem_u32(sm);
    uint32_t mb0 = smem_u32(&s_mbar[0]);
    int tid = threadIdx.x;
    int bid = blockIdx.x;

    if (bid < 128) {
        // ======== MID ROLE ========
        int z, t0, t1;
        if (bid < 64) {
            z = bid >> 3;
            int by = bid & 7;
            const char* Ab = g_pqimg + (size_t)(z * 8 + by) * (8 * 20480);
            gemm_body<8, true, 5>(Ab, g_wphimg, sm, mb0, z, by, 0, bph, g_pgimg, tid);
            t0 = 2 * by; t1 = 2 * by + 1;
        } else {
            int i = bid - 64;
            z = i >> 3;
            int bx = i & 7;
            const char* Bb = g_pvimg + (size_t)(z * 8 + bx) * (8 * 10240);
            gemm_body<8, false, 6>(g_wgimg, Bb, sm, mb0, z, 0, bx, bg, g_pgimg, tid);
            t0 = 2 * bx; t1 = 2 * bx + 1;
        }
        __syncthreads();
        if (tid == 0) {
            __threadfence();
            atomicAdd(&g_sync[z * 16 + t0], 1);
            atomicAdd(&g_sync[z * 16 + t1], 1);
        }
        return;
    }

    // ======== FLASH ROLE ========
    int fb = bid - 128;
    int lane = tid & 31, w = tid >> 5;
    int b = fb >> 5;
    int nt = fb & 31;
    const uint32_t STGSZ = 61440;
    const char* kimgT = g_kimg + (size_t)(b * 32 + nt) * 8 * 20480;
    const char* pgB = g_pgimg + (size_t)b * 16 * 61440;

    if (tid == 0) { MBAR_INIT(mb0, 1); MBAR_INIT(mb0 + 8, 1); MBAR_INIT(mb0 + 16, 1); }
    __syncthreads();

    // chunk counter t: 0..7 prologue (k+Wth), 8..23 main (phi+g)
    auto issue = [&](int t) {
        uint32_t st = sbase + (uint32_t)(t % 3) * STGSZ;
        uint32_t mb = mb0 + (uint32_t)(t % 3) * 8;
        if (t < 8) {
            MBAR_EXPECT(mb, 40960u);
            cpbulk(st, kimgT + (size_t)t * 20480, 20480, mb);
            cpbulk(st + 20480, g_wthimg + (size_t)t * 20480, 20480, mb);
        } else {
            // wait for mid role to publish this pg tile
            volatile int* fl = &g_sync[b * 16 + (t - 8)];
            while (*fl < 2) { __nanosleep(64); }
            __threadfence();
            MBAR_EXPECT(mb, 61440u);
            cpbulk(st, pgB + (size_t)(t - 8) * 61440, 61440, mb);
        }
    };
    if (tid == 0) { issue(0); issue(1); issue(2); }

    // ======== PROLOGUE: theta = kT.Wth^T (3-pass split) ========
    float acc[16][4];
#pragma unroll
    for (int j = 0; j < 16; j++)
#pragma unroll
        for (int e = 0; e < 4; e++) acc[j][e] = 0.f;

    for (int ch = 0; ch < 8; ch++) {
        mbar_wait(mb0 + (uint32_t)(ch % 3) * 8, (uint32_t)((ch / 3) & 1));
        uint32_t st = sbase + (uint32_t)(ch % 3) * STGSZ;
#pragma unroll
        for (int k16 = 0; k16 < 2; k16++) {
            uint32_t coff = (uint32_t)(k16 * 32 + (lane >> 4) * 16);
            uint32_t arow = (uint32_t)(w * 16 + (lane & 15)) * 80;
            uint32_t ah[4], al[4];
            ldsm4(ah[0], ah[1], ah[2], ah[3], st + arow + coff);
            ldsm4(al[0], al[1], al[2], al[3], st + 10240 + arow + coff);
#pragma unroll
            for (int nh = 0; nh < 8; nh++) {
                uint32_t brow = (uint32_t)(nh * 16 + (lane & 15)) * 80;
                uint32_t r0, r1, r2, r3;
                uint32_t bh0[2], bh1[2], bl0[2], bl1[2];
                ldsm4(r0, r1, r2, r3, st + 20480 + brow + coff);
                bh0[0] = r0; bh0[1] = r2; bh1[0] = r1; bh1[1] = r3;
                ldsm4(r0, r1, r2, r3, st + 30720 + brow + coff);
                bl0[0] = r0; bl0[1] = r2; bl1[0] = r1; bl1[1] = r3;
                mma16816(acc[2 * nh], ah, bh0);
                mma16816(acc[2 * nh + 1], ah, bh1);
                mma16816(acc[2 * nh], ah, bl0);
                mma16816(acc[2 * nh + 1], ah, bl1);
                mma16816(acc[2 * nh], al, bh0);
                mma16816(acc[2 * nh + 1], al, bh1);
            }
        }
        __syncthreads();
        if (tid == 0) issue(ch + 3);
    }

    // bias + hi/lo split -> A-fragments
    uint32_t th_hi[8][4], th_lo[8][4];
    {
        int t2 = (lane & 3) * 2;
#pragma unroll
        for (int s = 0; s < 8; s++) {
#pragma unroll
            for (int hf = 0; hf < 2; hf++) {
                int nb = 2 * s + hf;
                float b0 = bth[8 * nb + t2], b1 = bth[8 * nb + t2 + 1];
                float x0 = acc[nb][0] + b0, x1 = acc[nb][1] + b1;
                float x2 = acc[nb][2] + b0, x3 = acc[nb][3] + b1;
                __half hx0 = __float2half_rn(x0), hx1 = __float2half_rn(x1);
                __half hx2 = __float2half_rn(x2), hx3 = __float2half_rn(x3);
                th_hi[s][2 * hf + 0] = ((uint32_t)*(uint16_t*)&hx1 << 16) | *(uint16_t*)&hx0;
                th_hi[s][2 * hf + 1] = ((uint32_t)*(uint16_t*)&hx3 << 16) | *(uint16_t*)&hx2;
                th_lo[s][2 * hf + 0] = pkh2(x0 - __half2float(hx0), x1 - __half2float(hx1));
                th_lo[s][2 * hf + 1] = pkh2(x2 - __half2float(hx2), x3 - __half2float(hx3));
            }
        }
    }

    // ======== MAIN LOOP: S -> online softmax -> y ========
    float yacc[16][4];
#pragma unroll
    for (int j = 0; j < 16; j++)
#pragma unroll
        for (int e = 0; e < 4; e++) yacc[j][e] = 0.f;
    float rmax0 = -1e30f, rmax1 = -1e30f, rsum0 = 0.f, rsum1 = 0.f;

    for (int mt = 0; mt < 16; mt++) {
        int t = 8 + mt;
        mbar_wait(mb0 + (uint32_t)(t % 3) * 8, (uint32_t)((t / 3) & 1));
        uint32_t st = sbase + (uint32_t)(t % 3) * STGSZ;

        float sacc[8][4];
#pragma unroll
        for (int j = 0; j < 8; j++)
#pragma unroll
            for (int e = 0; e < 4; e++) sacc[j][e] = 0.f;

#pragma unroll
        for (int s = 0; s < 8; s++) {
            uint32_t chunk = (uint32_t)(s >> 1);
            uint32_t inner = (uint32_t)((s & 1) * 32 + (lane >> 4) * 16);
#pragma unroll
            for (int p = 0; p < 4; p++) {
                uint32_t brow = (uint32_t)(p * 16 + (lane & 15)) * 80;
                uint32_t bad = st + chunk * 5120 + brow + inner;
                uint32_t r0, r1, r2, r3;
                uint32_t bh0[2], bh1[2], bl0[2], bl1[2];
                ldsm4(r0, r1, r2, r3, bad);
                bh0[0] = r0; bh0[1] = r2; bh1[0] = r1; bh1[1] = r3;
                ldsm4(r0, r1, r2, r3, bad + 20480);
                bl0[0] = r0; bl0[1] = r2; bl1[0] = r1; bl1[1] = r3;
                mma16816(sacc[2 * p], th_hi[s], bh0);
                mma16816(sacc[2 * p + 1], th_hi[s], bh1);
                mma16816(sacc[2 * p], th_hi[s], bl0);
                mma16816(sacc[2 * p + 1], th_hi[s], bl1);
                mma16816(sacc[2 * p], th_lo[s], bh0);
                mma16816(sacc[2 * p + 1], th_lo[s], bh1);
            }
        }

        float tm0 = -1e30f, tm1 = -1e30f;
#pragma unroll
        for (int j = 0; j < 8; j++) {
            tm0 = fmaxf(tm0, fmaxf(sacc[j][0], sacc[j][1]));
            tm1 = fmaxf(tm1, fmaxf(sacc[j][2], sacc[j][3]));
        }
        tm0 = fmaxf(tm0, __shfl_xor_sync(0xffffffffu, tm0, 1));
        tm0 = fmaxf(tm0, __shfl_xor_sync(0xffffffffu, tm0, 2));
        tm1 = fmaxf(tm1, __shfl_xor_sync(0xffffffffu, tm1, 1));
        tm1 = fmaxf(tm1, __shfl_xor_sync(0xffffffffu, tm1, 2));
        float mn0 = fmaxf(rmax0, tm0), mn1 = fmaxf(rmax1, tm1);
        float sc0 = __expf(rmax0 - mn0), sc1 = __expf(rmax1 - mn1);
        float ts0 = 0.f, ts1 = 0.f;
#pragma unroll
        for (int j = 0; j < 8; j++) {
            sacc[j][0] = __expf(sacc[j][0] - mn0);
            sacc[j][1] = __expf(sacc[j][1] - mn0);
            sacc[j][2] = __expf(sacc[j][2] - mn1);
            sacc[j][3] = __expf(sacc[j][3] - mn1);
            ts0 += sacc[j][0] + sacc[j][1];
            ts1 += sacc[j][2] + sacc[j][3];
        }
        ts0 += __shfl_xor_sync(0xffffffffu, ts0, 1);
        ts0 += __shfl_xor_sync(0xffffffffu, ts0, 2);
        ts1 += __shfl_xor_sync(0xffffffffu, ts1, 1);
        ts1 += __shfl_xor_sync(0xffffffffu, ts1, 2);
        rsum0 = rsum0 * sc0 + ts0;
        rsum1 = rsum1 * sc1 + ts1;
        rmax0 = mn0; rmax1 = mn1;
#pragma unroll
        for (int j = 0; j < 16; j++) {
            yacc[j][0] *= sc0; yacc[j][1] *= sc0;
            yacc[j][2] *= sc1; yacc[j][3] *= sc1;
        }

        uint32_t pf[4][4];
#pragma unroll
        for (int s2 = 0; s2 < 4; s2++) {
            pf[s2][0] = pkh2(sacc[2 * s2][0], sacc[2 * s2][1]);
            pf[s2][1] = pkh2(sacc[2 * s2][2], sacc[2 * s2][3]);
            pf[s2][2] = pkh2(sacc[2 * s2 + 1][0], sacc[2 * s2 + 1][1]);
            pf[s2][3] = pkh2(sacc[2 * s2 + 1][2], sacc[2 * s2 + 1][3]);
        }

#pragma unroll
        for (int s2 = 0; s2 < 4; s2++) {
            uint32_t chunk = (uint32_t)(s2 >> 1);
            uint32_t inner = (uint32_t)((s2 & 1) * 32 + (lane >> 4) * 16);
#pragma unroll
            for (int pc = 0; pc < 8; pc++) {
                uint32_t brow = (uint32_t)(pc * 16 + (lane & 15)) * 80;
                uint32_t r0, r1, r2, r3;
                ldsm4(r0, r1, r2, r3, st + 40960 + chunk * 10240 + brow + inner);
                uint32_t bb0[2] = {r0, r2};
                uint32_t bb1[2] = {r1, r3};
                mma16816(yacc[2 * pc], pf[s2], bb0);
                mma16816(yacc[2 * pc + 1], pf[s2], bb1);
            }
        }
        __syncthreads();
        if (tid == 0 && t + 3 < 24) issue(t + 3);
    }

    // ======== EPILOGUE: pack y into B-frags, out = BN(Ww.y^T) + v ========
    float inv0 = 1.f / rsum0, inv1 = 1.f / rsum1;
    uint32_t yB[8][2][2];
#pragma unroll
    for (int s = 0; s < 8; s++) {
        yB[s][0][0] = pkh2(yacc[2 * s][0] * inv0, yacc[2 * s][1] * inv0);
        yB[s][0][1] = pkh2(yacc[2 * s + 1][0] * inv0, yacc[2 * s + 1][1] * inv0);
        yB[s][1][0] = pkh2(yacc[2 * s][2] * inv1, yacc[2 * s][3] * inv1);
        yB[s][1][1] = pkh2(yacc[2 * s + 1][2] * inv1, yacc[2 * s + 1][3] * inv1);
    }

    // pull full Ww image (80KB) into stage smem (slot0, 9th completion -> parity 0)
    if (tid == 0) {
        MBAR_EXPECT(mb0, 81920u);
        cpbulk(sbase, g_wwimg, 81920, mb0);
    }
    mbar_wait(mb0, 0u);

    int r = lane >> 2, c2 = (lane & 3) * 2;
    int nbase = nt * 128 + w * 16;
#pragma unroll
    for (int coh = 0; coh < 2; coh++) {
        float oacc[8][2][4];
#pragma unroll
        for (int ct = 0; ct < 8; ct++)
#pragma unroll
            for (int nf = 0; nf < 2; nf++)
#pragma unroll
                for (int e = 0; e < 4; e++) oacc[ct][nf][e] = 0.f;

#pragma unroll
        for (int s = 0; s < 8; s++) {
            uint32_t coff = (uint32_t)((s & 1) * 32 + (lane >> 4) * 16);
            uint32_t rbase = sbase + (uint32_t)(coh * 4 + (s >> 1)) * 10240;
#pragma unroll
            for (int ct = 0; ct < 8; ct++) {
                uint32_t a[4];
                ldsm4(a[0], a[1], a[2], a[3],
                      rbase + (uint32_t)(ct * 16 + (lane & 15)) * 80 + coff);
                mma16816(oacc[ct][0], a, yB[s][0]);
                mma16816(oacc[ct][1], a, yB[s][1]);
            }
        }

#pragma unroll
        for (int ct = 0; ct < 8; ct++) {
#pragma unroll
            for (int h = 0; h < 2; h++) {
                int co = coh * 128 + ct * 16 + h * 8 + r;
                float s1 = g_bns[co], t1 = g_bnt[co];
                size_t rowb = (size_t)b * CC * NPIX + (size_t)co * NPIX;
#pragma unroll
                for (int nf = 0; nf < 2; nf++) {
                    int n = nbase + nf * 8 + c2;
                    float2 rr = *(const float2*)(vres + rowb + n);
                    float v0 = oacc[ct][nf][h * 2 + 0] * s1 + t1 + rr.x;
                    float v1 = oacc[ct][nf][h * 2 + 1] * s1 + t1 + rr.y;
                    *(float2*)(out + rowb + n) = make_float2(v0, v1);
                }
            }
        }
    }
}

// ---------------- merged prep: pooltrans (0..4095) + transk (4096..12287) + wprep ----------------
__global__ void __launch_bounds__(256) prep_kernel(
    const float* __restrict__ q, const float* __restrict__ v, const float* __restrict__ k,
    const float* __restrict__ Wth, const float* __restrict__ Wph,
    const float* __restrict__ Wg, const float* __restrict__ Ww,
    const float* __restrict__ gamma, const float* __restrict__ beta,
    const float* __restrict__ mean, const float* __restrict__ var,
    const float* __restrict__ bw) {
    __shared__ float ts[32][33];
    int bid = blockIdx.x;
    int tid = threadIdx.x;
    int tx = tid & 31, ty = tid >> 5;

    if (bid < 4096) {
        int z = bid >> 8, rem = bid & 255;
        int m0 = (rem & 31) * 32, c0 = (rem >> 5) * 32;
        bool isq = (z < BB);
        const float* src = isq ? q : v;
        int b = z & (BB - 1);
        const float* sb = src + (size_t)b * CC * NPIX;
        int m = m0 + tx, mi = m >> 5, mj = m & 31;
#pragma unroll
        for (int i = 0; i < 4; i++) {
            int c = c0 + ty + i * 8;
            const float* p = sb + (size_t)c * NPIX + (2 * mi) * WW + 2 * mj;
            ts[ty + i * 8][tx] = 0.25f * (p[0] + p[1] + p[WW] + p[WW + 1]);
        }
        __syncthreads();
        int ch = c0 >> 5;
#pragma unroll
        for (int i = 0; i < 4; i++) {
            float val = ts[tx][ty + i * 8];
            int mm = m0 + ty + i * 8;
            int mtile = mm >> 7, r = mm & 127;
            uint32_t off = lane_off(r, tx);
            __half h = __float2half_rn(val);
            if (isq) {
                char* base = g_pqimg + (size_t)((b * 8 + mtile) * 8 + ch) * 20480;
                *(__half*)(base + off) = h;
                *(__half*)(base + 10240 + off) = __float2half_rn(val - __half2float(h));
            } else {
                *(__half*)(g_pvimg + (size_t)((b * 8 + mtile) * 8 + ch) * 10240 + off) = h;
            }
        }
    } else if (bid < 12288) {
        int i = bid - 4096;
        int b = i >> 10;
        int n0 = (i & 127) * 32, c0 = ((i >> 7) & 7) * 32;
        const float* sb = k + (size_t)b * CC * NPIX;
#pragma unroll
        for (int j = 0; j < 4; j++)
            ts[ty + j * 8][tx] = sb[(size_t)(c0 + ty + j * 8) * NPIX + n0 + tx];
        __syncthreads();
        int ch = c0 >> 5;
#pragma unroll
        for (int j = 0; j < 4; j++) {
            float val = ts[tx][ty + j * 8];
            int nn = n0 + ty + j * 8;
            int nt = nn >> 7, r = nn & 127;
            uint32_t off = lane_off(r, tx);
            char* base = g_kimg + (size_t)((b * 32 + nt) * 8 + ch) * 20480;
            __half h = __float2half_rn(val);
            *(__half*)(base + off) = h;
            *(__half*)(base + 10240 + off) = __float2half_rn(val - __half2float(h));
        }
    } else {
        int i = (bid - 12288) * 256 + tid;
        {
            int row = i >> 8, c = i & 255;
            int ch = c >> 5, cc = c & 31;
            uint32_t off = lane_off(row, cc);
            float a = Wth[i];
            __half h = __float2half_rn(a);
            *(__half*)(g_wthimg + ch * 20480 + off) = h;
            *(__half*)(g_wthimg + ch * 20480 + 10240 + off) = __float2half_rn(a - __half2float(h));
            float p = Wph[i];
            __half hp = __float2half_rn(p);
            *(__half*)(g_wphimg + ch * 20480 + off) = hp;
            *(__half*)(g_wphimg + ch * 20480 + 10240 + off) = __float2half_rn(p - __half2float(hp));
            *(__half*)(g_wgimg + ch * 10240 + off) = __float2half_rn(Wg[i]);
        }
        {
            int row = i >> 7, ci = i & 127;
            int rt = row >> 7, rr = row & 127;
            int ch = ci >> 5, cc = ci & 31;
            *(__half*)(g_wwimg + (rt * 4 + ch) * 10240 + lane_off(rr, cc)) = __float2half_rn(Ww[i]);
        }
        if (i < CC) {
            float sc = gamma[i] * rsqrtf(var[i] + 1e-5f);
            g_bns[i] = sc;
            g_bnt[i] = beta[i] + (bw[i] - mean[i]) * sc;
        }
        if (i < BB * 16) g_sync[i] = 0;   // reset cross-role flags every run
    }
}

// ---------------- launch ----------------
extern "C" void kernel_launch(void* const* d_in, const int* in_sizes, int n_in,
                              void* d_out, int out_size) {
    (void)in_sizes; (void)n_in; (void)out_size;
    const float* q     = (const float*)d_in[0];
    const float* k     = (const float*)d_in[1];
    const float* v     = (const float*)d_in[2];
    const float* Wg    = (const float*)d_in[3];
    const float* bg    = (const float*)d_in[4];
    const float* Wth   = (const float*)d_in[5];
    const float* bth   = (const float*)d_in[6];
    const float* Wph   = (const float*)d_in[7];
    const float* bph   = (const float*)d_in[8];
    const float* Ww    = (const float*)d_in[9];
    const float* bw    = (const float*)d_in[10];
    const float* gamma = (const float*)d_in[11];
    const float* beta  = (const float*)d_in[12];
    const float* mean  = (const float*)d_in[13];
    const float* var   = (const float*)d_in[14];
    float* out = (float*)d_out;

    const int SMF = 184320;  // 3 x 61440 (flash role; mid role uses a subset)
    cudaFuncSetAttribute(midflash_kernel, cudaFuncAttributeMaxDynamicSharedMemorySize, SMF);

    // 1) merged prep -> images (+ flag reset)
    prep_kernel<<<12416, 256>>>(q, v, k, Wth, Wph, Wg, Ww, gamma, beta, mean, var, bw);
    // 2) merged mid (blocks 0-127) + flash (blocks 128-383) with flag handoff
    midflash_kernel<<<384, 256, SMF>>>(bph, bg, bth, v, out);
}

// round 15
// speedup vs baseline: 1.0135x; 1.0135x over previous
#include <cuda_runtime.h>
#include <cuda_fp16.h>
#include <cstdint>
#include <cstddef>

// Problem dims
#define BB   8
#define CC   256
#define CHI  128
#define HH   64
#define WW   64
#define NPIX 4096   // H*W
#define MPOOL 1024  // (H/2)*(W/2)

// ---------------- gmem "smem-image" buffers ----------------
// lane_off(r, c<32) = r*80 + (c>>3)*16 + (c&7)*2
__device__ __align__(128) char g_kimg[(size_t)8 * 32 * 8 * 20480];
__device__ __align__(128) char g_wthimg[8 * 20480];
__device__ __align__(128) char g_wphimg[8 * 20480];
__device__ __align__(128) char g_wgimg[8 * 10240];
__device__ __align__(128) char g_wwimg[8 * 10240];
__device__ __align__(128) char g_pqimg[(size_t)8 * 8 * 8 * 20480];
__device__ __align__(128) char g_pvimg[(size_t)8 * 8 * 8 * 10240];
// pgimg: per (b, mt64) 61440 = [phi_hi 4ch x 64x80 | phi_lo | g 2ch x 128x80]
__device__ __align__(128) char g_pgimg[(size_t)8 * 16 * 61440];
__device__ float g_bns[CC];
__device__ float g_bnt[CC];

// ---------------- PTX helpers ----------------
__device__ __forceinline__ uint32_t smem_u32(const void* p) {
    uint32_t a;
    asm("{ .reg .u64 t; cvta.to.shared.u64 t, %1; cvt.u32.u64 %0, t; }" : "=r"(a) : "l"(p));
    return a;
}
__device__ __forceinline__ void cpbulk(uint32_t dst, const void* src, uint32_t bytes,
                                       uint32_t mbar) {
    asm volatile(
        "cp.async.bulk.shared::cluster.global.mbarrier::complete_tx::bytes [%0], [%1], %2, [%3];"
        :: "r"(dst), "l"(src), "r"(bytes), "r"(mbar) : "memory");
}
#define MBAR_INIT(mb, n) \
    asm volatile("mbarrier.init.shared.b64 [%0], %1;" :: "r"(mb), "r"((uint32_t)(n)) : "memory")
#define MBAR_EXPECT(mb, n) \
    asm volatile("mbarrier.arrive.expect_tx.shared.b64 _, [%0], %1;" :: "r"(mb), "r"((uint32_t)(n)) : "memory")

__device__ __forceinline__ void mbar_wait(uint32_t mb, uint32_t parity) {
    uint32_t done;
    asm volatile(
        "{\n\t.reg .pred p;\n\t"
        "mbarrier.try_wait.parity.acquire.cta.shared::cta.b64 p, [%1], %2;\n\t"
        "selp.b32 %0, 1, 0, p;\n\t}"
        : "=r"(done) : "r"(mb), "r"(parity) : "memory");
    if (!done) {
        asm volatile(
            "{\n\t.reg .pred P1;\n\t"
            "W0_%=:\n\t"
            "mbarrier.try_wait.parity.acquire.cta.shared::cta.b64 P1, [%0], %1, 0x989680;\n\t"
            "@P1 bra.uni W1_%=;\n\t"
            "bra.uni W0_%=;\n\t"
            "W1_%=:\n\t}"
            :: "r"(mb), "r"(parity) : "memory");
    }
}
__device__ __forceinline__ void ldsm4(uint32_t& r0, uint32_t& r1, uint32_t& r2, uint32_t& r3,
                                      uint32_t a) {
    asm volatile("ldmatrix.sync.aligned.m8n8.x4.shared.b16 {%0,%1,%2,%3}, [%4];"
                 : "=r"(r0), "=r"(r1), "=r"(r2), "=r"(r3) : "r"(a));
}
__device__ __forceinline__ void mma16816(float* c, const uint32_t* a, const uint32_t* b) {
    asm volatile(
        "mma.sync.aligned.m16n8k16.row.col.f32.f16.f16.f32 "
        "{%0,%1,%2,%3}, {%4,%5,%6,%7}, {%8,%9}, {%0,%1,%2,%3};"
        : "+f"(c[0]), "+f"(c[1]), "+f"(c[2]), "+f"(c[3])
        : "r"(a[0]), "r"(a[1]), "r"(a[2]), "r"(a[3]), "r"(b[0]), "r"(b[1]));
}
__device__ __forceinline__ uint32_t pkh2(float a, float b) {
    __half2 h = __floats2half2_rn(a, b);
    return *(uint32_t*)&h;
}
__device__ __forceinline__ uint32_t lane_off(int r, int c) {
    return (uint32_t)(r * 80 + (c >> 3) * 16 + (c & 7) * 2);
}

// ---------------- 3-stage bulk-fed GEMM body (phi/g projections) ----------------
// EPI 5: phi -> pgimg (col bias, split hi/lo) | 6: g -> pgimg (row bias)
template <int NCH, bool SPLIT, int EPI>
__device__ __forceinline__ void gemm_body(
    const char* __restrict__ Ab, const char* __restrict__ Bb,
    char* smraw, uint32_t mb0, int z, int by, int bx,
    const float* __restrict__ bias, char* __restrict__ outImg, int tid) {
    constexpr uint32_t REG = SPLIT ? 20480 : 10240;
    constexpr uint32_t STAGE = SPLIT ? 40960 : 20480;
    uint32_t sbase = smem_u32(smraw);
    int lane = tid & 31, w = tid >> 5;
    int wm = w >> 2, wn = w & 3;

    if (tid == 0) { MBAR_INIT(mb0, 1); MBAR_INIT(mb0 + 8, 1); MBAR_INIT(mb0 + 16, 1); }
    __syncthreads();

    auto issue = [&](int ch) {
        uint32_t st = sbase + (uint32_t)(ch % 3) * STAGE;
        uint32_t mb = mb0 + (uint32_t)(ch % 3) * 8;
        MBAR_EXPECT(mb, SPLIT ? 40960u : 20480u);
        if (SPLIT) {
            cpbulk(st, Ab + (size_t)ch * REG, 10240, mb);
            cpbulk(st + 20480, Ab + (size_t)ch * REG + 10240, 10240, mb);
            cpbulk(st + 10240, Bb + (size_t)ch * REG, 10240, mb);
            cpbulk(st + 30720, Bb + (size_t)ch * REG + 10240, 10240, mb);
        } else {
            cpbulk(st, Ab + (size_t)ch * REG, 10240, mb);
            cpbulk(st + 10240, Bb + (size_t)ch * REG, 10240, mb);
        }
    };
    if (tid == 0) { issue(0); issue(1); issue(2); }

    float acc[4][4][4];
#pragma unroll
    for (int i = 0; i < 4; i++)
#pragma unroll
        for (int j = 0; j < 4; j++)
#pragma unroll
            for (int e = 0; e < 4; e++) acc[i][j][e] = 0.f;

    for (int ch = 0; ch < NCH; ch++) {
        mbar_wait(mb0 + (uint32_t)(ch % 3) * 8, (uint32_t)((ch / 3) & 1));
        uint32_t sa = sbase + (uint32_t)(ch % 3) * STAGE;
        uint32_t sb = sa + 10240;
#pragma unroll
        for (int k16 = 0; k16 < 2; k16++) {
            uint32_t a[4][4], b[4][2];
            uint32_t coff = (uint32_t)(k16 * 32 + (lane >> 4) * 16);
#pragma unroll
            for (int mi = 0; mi < 4; mi++) {
                uint32_t ad = sa + (uint32_t)(wm * 64 + mi * 16 + (lane & 15)) * 80 + coff;
                ldsm4(a[mi][0], a[mi][1], a[mi][2], a[mi][3], ad);
            }
#pragma unroll
            for (int nh = 0; nh < 2; nh++) {
                uint32_t bd = sb + (uint32_t)(wn * 32 + nh * 16 + (lane & 15)) * 80 + coff;
                uint32_t r0, r1, r2, r3;
                ldsm4(r0, r1, r2, r3, bd);
                b[nh * 2 + 0][0] = r0; b[nh * 2 + 0][1] = r2;
                b[nh * 2 + 1][0] = r1; b[nh * 2 + 1][1] = r3;
            }
#pragma unroll
            for (int mi = 0; mi < 4; mi++)
#pragma unroll
                for (int ni = 0; ni < 4; ni++) mma16816(acc[mi][ni], a[mi], b[ni]);
            if (SPLIT) {
                uint32_t al[4][4], bl[4][2];
#pragma unroll
                for (int mi = 0; mi < 4; mi++) {
                    uint32_t ad = sa + 20480 + (uint32_t)(wm * 64 + mi * 16 + (lane & 15)) * 80 + coff;
                    ldsm4(al[mi][0], al[mi][1], al[mi][2], al[mi][3], ad);
                }
#pragma unroll
                for (int nh = 0; nh < 2; nh++) {
                    uint32_t bd = sa + 30720 + (uint32_t)(wn * 32 + nh * 16 + (lane & 15)) * 80 + coff;
                    uint32_t r0, r1, r2, r3;
                    ldsm4(r0, r1, r2, r3, bd);
                    bl[nh * 2 + 0][0] = r0; bl[nh * 2 + 0][1] = r2;
                    bl[nh * 2 + 1][0] = r1; bl[nh * 2 + 1][1] = r3;
                }
#pragma unroll
                for (int mi = 0; mi < 4; mi++)
#pragma unroll
                    for (int ni = 0; ni < 4; ni++) {
                        mma16816(acc[mi][ni], a[mi], bl[ni]);
                        mma16816(acc[mi][ni], al[mi], b[ni]);
                    }
            }
        }
        __syncthreads();
        if (tid == 0 && ch + 3 < NCH) issue(ch + 3);
    }

    int r = lane >> 2, cp2 = (lane & 3) * 2;
    int row0 = by * 128 + wm * 64;
    int col0 = bx * 128 + wn * 32;
#pragma unroll
    for (int mi = 0; mi < 4; mi++) {
#pragma unroll
        for (int h = 0; h < 2; h++) {
            int row = row0 + mi * 16 + h * 8 + r;
            float t = (EPI == 6) ? bias[row] : 0.f;
#pragma unroll
            for (int ni = 0; ni < 4; ni++) {
                int col = col0 + ni * 8 + cp2;
                float v0 = acc[mi][ni][h * 2 + 0];
                float v1 = acc[mi][ni][h * 2 + 1];
                if (EPI == 5) {
                    v0 += bias[col]; v1 += bias[col + 1];
                    __half h0 = __float2half_rn(v0), h1 = __float2half_rn(v1);
                    uint32_t hi = ((uint32_t)*(uint16_t*)&h1 << 16) | *(uint16_t*)&h0;
                    uint32_t lo = pkh2(v0 - __half2float(h0), v1 - __half2float(h1));
                    char* base = outImg + (size_t)(z * 16 + (row >> 6)) * 61440;
                    uint32_t off = (uint32_t)(col >> 5) * 5120 + lane_off(row & 63, col & 31);
                    *(uint32_t*)(base + off) = hi;
                    *(uint32_t*)(base + off + 20480) = lo;
                } else {
                    uint32_t hv = pkh2(v0 + t, v1 + t);
                    char* base = outImg + (size_t)(z * 16 + (col >> 6)) * 61440 + 40960;
                    uint32_t off = (uint32_t)((col >> 5) & 1) * 10240 + lane_off(row, col & 31);
                    *(uint32_t*)(base + off) = hv;
                }
            }
        }
    }
}

// ---------------- mid kernel: phi (blocks 0-63) + g (blocks 64-127) ----------------
__global__ void __launch_bounds__(256, 1) mid_kernel(const float* __restrict__ bph,
                                                     const float* __restrict__ bg) {
    extern __shared__ char sm[];
    __shared__ __align__(8) uint64_t s_mbar[3];
    int tid = threadIdx.x;
    uint32_t mb0 = smem_u32(&s_mbar[0]);
    if (blockIdx.x < 64) {
        int z = blockIdx.x >> 3, by = blockIdx.x & 7;
        const char* Ab = g_pqimg + (size_t)(z * 8 + by) * (8 * 20480);
        gemm_body<8, true, 5>(Ab, g_wphimg, sm, mb0, z, by, 0, bph, g_pgimg, tid);
    } else {
        int i = blockIdx.x - 64;
        int z = i >> 3, bx = i & 7;
        const char* Bb = g_pvimg + (size_t)(z * 8 + bx) * (8 * 10240);
        gemm_body<8, false, 6>(g_wgimg, Bb, sm, mb0, z, 0, bx, bg, g_pgimg, tid);
    }
}

// ---------------- fused flash: theta prologue + S-softmax-y + final Ww GEMM + BN + resid ----------------
__global__ void __launch_bounds__(256, 1) flash_kernel(const float* __restrict__ bth,
                                                       const float* __restrict__ vres,
                                                       float* __restrict__ out) {
    extern __shared__ char sm[];
    __shared__ __align__(8) uint64_t s_mbar[3];
    uint32_t sbase = smem_u32(sm);
    uint32_t mb0 = smem_u32(&s_mbar[0]);
    const uint32_t STGSZ = 61440;

    int tid = threadIdx.x, lane = tid & 31, w = tid >> 5;
    int b = blockIdx.y;
    int nt = blockIdx.x;
    const char* kimgT = g_kimg + (size_t)(b * 32 + nt) * 8 * 20480;
    const char* pgB = g_pgimg + (size_t)b * 16 * 61440;

    if (tid == 0) { MBAR_INIT(mb0, 1); MBAR_INIT(mb0 + 8, 1); MBAR_INIT(mb0 + 16, 1); }
    __syncthreads();

    // chunk counter t: 0..7 prologue (k+Wth), 8..23 main (phi+g)
    auto issue = [&](int t) {
        uint32_t st = sbase + (uint32_t)(t % 3) * STGSZ;
        uint32_t mb = mb0 + (uint32_t)(t % 3) * 8;
        if (t < 8) {
            MBAR_EXPECT(mb, 40960u);
            cpbulk(st, kimgT + (size_t)t * 20480, 20480, mb);
            cpbulk(st + 20480, g_wthimg + (size_t)t * 20480, 20480, mb);
        } else {
            MBAR_EXPECT(mb, 61440u);
            cpbulk(st, pgB + (size_t)(t - 8) * 61440, 61440, mb);
        }
    };
    if (tid == 0) { issue(0); issue(1); issue(2); }

    // ======== PROLOGUE: theta = kT.Wth^T (3-pass split) ========
    float acc[16][4];
#pragma unroll
    for (int j = 0; j < 16; j++)
#pragma unroll
        for (int e = 0; e < 4; e++) acc[j][e] = 0.f;

    for (int ch = 0; ch < 8; ch++) {
        mbar_wait(mb0 + (uint32_t)(ch % 3) * 8, (uint32_t)((ch / 3) & 1));
        uint32_t st = sbase + (uint32_t)(ch % 3) * STGSZ;
#pragma unroll
        for (int k16 = 0; k16 < 2; k16++) {
            uint32_t coff = (uint32_t)(k16 * 32 + (lane >> 4) * 16);
            uint32_t arow = (uint32_t)(w * 16 + (lane & 15)) * 80;
            uint32_t ah[4], al[4];
            ldsm4(ah[0], ah[1], ah[2], ah[3], st + arow + coff);
            ldsm4(al[0], al[1], al[2], al[3], st + 10240 + arow + coff);
#pragma unroll
            for (int nh = 0; nh < 8; nh++) {
                uint32_t brow = (uint32_t)(nh * 16 + (lane & 15)) * 80;
                uint32_t r0, r1, r2, r3;
                uint32_t bh0[2], bh1[2], bl0[2], bl1[2];
                ldsm4(r0, r1, r2, r3, st + 20480 + brow + coff);
                bh0[0] = r0; bh0[1] = r2; bh1[0] = r1; bh1[1] = r3;
                ldsm4(r0, r1, r2, r3, st + 30720 + brow + coff);
                bl0[0] = r0; bl0[1] = r2; bl1[0] = r1; bl1[1] = r3;
                mma16816(acc[2 * nh], ah, bh0);
                mma16816(acc[2 * nh + 1], ah, bh1);
                mma16816(acc[2 * nh], ah, bl0);
                mma16816(acc[2 * nh + 1], ah, bl1);
                mma16816(acc[2 * nh], al, bh0);
                mma16816(acc[2 * nh + 1], al, bh1);
            }
        }
        __syncthreads();
        if (tid == 0) issue(ch + 3);
    }

    // bias + hi/lo split -> A-fragments
    uint32_t th_hi[8][4], th_lo[8][4];
    {
        int t2 = (lane & 3) * 2;
#pragma unroll
        for (int s = 0; s < 8; s++) {
#pragma unroll
            for (int hf = 0; hf < 2; hf++) {
                int nb = 2 * s + hf;
                float b0 = bth[8 * nb + t2], b1 = bth[8 * nb + t2 + 1];
                float x0 = acc[nb][0] + b0, x1 = acc[nb][1] + b1;
                float x2 = acc[nb][2] + b0, x3 = acc[nb][3] + b1;
                __half hx0 = __float2half_rn(x0), hx1 = __float2half_rn(x1);
                __half hx2 = __float2half_rn(x2), hx3 = __float2half_rn(x3);
                th_hi[s][2 * hf + 0] = ((uint32_t)*(uint16_t*)&hx1 << 16) | *(uint16_t*)&hx0;
                th_hi[s][2 * hf + 1] = ((uint32_t)*(uint16_t*)&hx3 << 16) | *(uint16_t*)&hx2;
                th_lo[s][2 * hf + 0] = pkh2(x0 - __half2float(hx0), x1 - __half2float(hx1));
                th_lo[s][2 * hf + 1] = pkh2(x2 - __half2float(hx2), x3 - __half2float(hx3));
            }
        }
    }

    // ======== MAIN LOOP: S -> online softmax -> y ========
    float yacc[16][4];
#pragma unroll
    for (int j = 0; j < 16; j++)
#pragma unroll
        for (int e = 0; e < 4; e++) yacc[j][e] = 0.f;
    float rmax0 = -1e30f, rmax1 = -1e30f, rsum0 = 0.f, rsum1 = 0.f;

    for (int mt = 0; mt < 16; mt++) {
        int t = 8 + mt;
        mbar_wait(mb0 + (uint32_t)(t % 3) * 8, (uint32_t)((t / 3) & 1));
        uint32_t st = sbase + (uint32_t)(t % 3) * STGSZ;

        float sacc[8][4];
#pragma unroll
        for (int j = 0; j < 8; j++)
#pragma unroll
            for (int e = 0; e < 4; e++) sacc[j][e] = 0.f;

#pragma unroll
        for (int s = 0; s < 8; s++) {
            uint32_t chunk = (uint32_t)(s >> 1);
            uint32_t inner = (uint32_t)((s & 1) * 32 + (lane >> 4) * 16);
#pragma unroll
            for (int p = 0; p < 4; p++) {
                uint32_t brow = (uint32_t)(p * 16 + (lane & 15)) * 80;
                uint32_t bad = st + chunk * 5120 + brow + inner;
                uint32_t r0, r1, r2, r3;
                uint32_t bh0[2], bh1[2], bl0[2], bl1[2];
                ldsm4(r0, r1, r2, r3, bad);
                bh0[0] = r0; bh0[1] = r2; bh1[0] = r1; bh1[1] = r3;
                ldsm4(r0, r1, r2, r3, bad + 20480);
                bl0[0] = r0; bl0[1] = r2; bl1[0] = r1; bl1[1] = r3;
                mma16816(sacc[2 * p], th_hi[s], bh0);
                mma16816(sacc[2 * p + 1], th_hi[s], bh1);
                mma16816(sacc[2 * p], th_hi[s], bl0);
                mma16816(sacc[2 * p + 1], th_hi[s], bl1);
                mma16816(sacc[2 * p], th_lo[s], bh0);
                mma16816(sacc[2 * p + 1], th_lo[s], bh1);
            }
        }

        // ---- online softmax ----
        float tm0 = -1e30f, tm1 = -1e30f;
#pragma unroll
        for (int j = 0; j < 8; j++) {
            tm0 = fmaxf(tm0, fmaxf(sacc[j][0], sacc[j][1]));
            tm1 = fmaxf(tm1, fmaxf(sacc[j][2], sacc[j][3]));
        }
        tm0 = fmaxf(tm0, __shfl_xor_sync(0xffffffffu, tm0, 1));
        tm0 = fmaxf(tm0, __shfl_xor_sync(0xffffffffu, tm0, 2));
        tm1 = fmaxf(tm1, __shfl_xor_sync(0xffffffffu, tm1, 1));
        tm1 = fmaxf(tm1, __shfl_xor_sync(0xffffffffu, tm1, 2));
        float mn0 = fmaxf(rmax0, tm0), mn1 = fmaxf(rmax1, tm1);
        // Rescale only if some row's max advanced. When skipped, sc==1 exactly,
        // so this branch is bitwise-identical to the unconditional version.
        if (__any_sync(0xffffffffu, (mn0 > rmax0) | (mn1 > rmax1))) {
            float sc0 = __expf(rmax0 - mn0), sc1 = __expf(rmax1 - mn1);
            rsum0 *= sc0;
            rsum1 *= sc1;
#pragma unroll
            for (int j = 0; j < 16; j++) {
                yacc[j][0] *= sc0; yacc[j][1] *= sc0;
                yacc[j][2] *= sc1; yacc[j][3] *= sc1;
            }
            rmax0 = mn0; rmax1 = mn1;
        }
        float ts0 = 0.f, ts1 = 0.f;
#pragma unroll
        for (int j = 0; j < 8; j++) {
            sacc[j][0] = __expf(sacc[j][0] - rmax0);
            sacc[j][1] = __expf(sacc[j][1] - rmax0);
            sacc[j][2] = __expf(sacc[j][2] - rmax1);
            sacc[j][3] = __expf(sacc[j][3] - rmax1);
            ts0 += sacc[j][0] + sacc[j][1];
            ts1 += sacc[j][2] + sacc[j][3];
        }
        ts0 += __shfl_xor_sync(0xffffffffu, ts0, 1);
        ts0 += __shfl_xor_sync(0xffffffffu, ts0, 2);
        ts1 += __shfl_xor_sync(0xffffffffu, ts1, 1);
        ts1 += __shfl_xor_sync(0xffffffffu, ts1, 2);
        rsum0 += ts0;
        rsum1 += ts1;

        uint32_t pf[4][4];
#pragma unroll
        for (int s2 = 0; s2 < 4; s2++) {
            pf[s2][0] = pkh2(sacc[2 * s2][0], sacc[2 * s2][1]);
            pf[s2][1] = pkh2(sacc[2 * s2][2], sacc[2 * s2][3]);
            pf[s2][2] = pkh2(sacc[2 * s2 + 1][0], sacc[2 * s2 + 1][1]);
            pf[s2][3] = pkh2(sacc[2 * s2 + 1][2], sacc[2 * s2 + 1][3]);
        }

#pragma unroll
        for (int s2 = 0; s2 < 4; s2++) {
            uint32_t chunk = (uint32_t)(s2 >> 1);
            uint32_t inner = (uint32_t)((s2 & 1) * 32 + (lane >> 4) * 16);
#pragma unroll
            for (int pc = 0; pc < 8; pc++) {
                uint32_t brow = (uint32_t)(pc * 16 + (lane & 15)) * 80;
                uint32_t r0, r1, r2, r3;
                ldsm4(r0, r1, r2, r3, st + 40960 + chunk * 10240 + brow + inner);
                uint32_t bb0[2] = {r0, r2};
                uint32_t bb1[2] = {r1, r3};
                mma16816(yacc[2 * pc], pf[s2], bb0);
                mma16816(yacc[2 * pc + 1], pf[s2], bb1);
            }
        }
        __syncthreads();
        if (tid == 0 && t + 3 < 24) issue(t + 3);
    }

    // ======== EPILOGUE: pack y into B-frags, out = BN(Ww.y^T) + v ========
    float inv0 = 1.f / rsum0, inv1 = 1.f / rsum1;
    uint32_t yB[8][2][2];
#pragma unroll
    for (int s = 0; s < 8; s++) {
        yB[s][0][0] = pkh2(yacc[2 * s][0] * inv0, yacc[2 * s][1] * inv0);
        yB[s][0][1] = pkh2(yacc[2 * s + 1][0] * inv0, yacc[2 * s + 1][1] * inv0);
        yB[s][1][0] = pkh2(yacc[2 * s][2] * inv1, yacc[2 * s][3] * inv1);
        yB[s][1][1] = pkh2(yacc[2 * s + 1][2] * inv1, yacc[2 * s + 1][3] * inv1);
    }

    // pull full Ww image (80KB) into stage smem (slot0, 9th completion -> parity 0)
    if (tid == 0) {
        MBAR_EXPECT(mb0, 81920u);
        cpbulk(sbase, g_wwimg, 81920, mb0);
    }
    mbar_wait(mb0, 0u);

    int r = lane >> 2, c2 = (lane & 3) * 2;
    int nbase = nt * 128 + w * 16;
#pragma unroll
    for (int coh = 0; coh < 2; coh++) {
        float oacc[8][2][4];
#pragma unroll
        for (int ct = 0; ct < 8; ct++)
#pragma unroll
            for (int nf = 0; nf < 2; nf++)
#pragma unroll
                for (int e = 0; e < 4; e++) oacc[ct][nf][e] = 0.f;

#pragma unroll
        for (int s = 0; s < 8; s++) {
            uint32_t coff = (uint32_t)((s & 1) * 32 + (lane >> 4) * 16);
            uint32_t rbase = sbase + (uint32_t)(coh * 4 + (s >> 1)) * 10240;
#pragma unroll
            for (int ct = 0; ct < 8; ct++) {
                uint32_t a[4];
                ldsm4(a[0], a[1], a[2], a[3],
                      rbase + (uint32_t)(ct * 16 + (lane & 15)) * 80 + coff);
                mma16816(oacc[ct][0], a, yB[s][0]);
                mma16816(oacc[ct][1], a, yB[s][1]);
            }
        }

#pragma unroll
        for (int ct = 0; ct < 8; ct++) {
#pragma unroll
            for (int h = 0; h < 2; h++) {
                int co = coh * 128 + ct * 16 + h * 8 + r;
                float s1 = g_bns[co], t1 = g_bnt[co];
                size_t rowb = (size_t)b * CC * NPIX + (size_t)co * NPIX;
#pragma unroll
                for (int nf = 0; nf < 2; nf++) {
                    int n = nbase + nf * 8 + c2;
                    float2 rr = *(const float2*)(vres + rowb + n);
                    float v0 = oacc[ct][nf][h * 2 + 0] * s1 + t1 + rr.x;
                    float v1 = oacc[ct][nf][h * 2 + 1] * s1 + t1 + rr.y;
                    *(float2*)(out + rowb + n) = make_float2(v0, v1);
                }
            }
        }
    }
}

// ---------------- merged prep: pooltrans (0..4095) + transk (4096..12287) + wprep ----------------
__global__ void __launch_bounds__(256) prep_kernel(
    const float* __restrict__ q, const float* __restrict__ v, const float* __restrict__ k,
    const float* __restrict__ Wth, const float* __restrict__ Wph,
    const float* __restrict__ Wg, const float* __restrict__ Ww,
    const float* __restrict__ gamma, const float* __restrict__ beta,
    const float* __restrict__ mean, const float* __restrict__ var,
    const float* __restrict__ bw) {
    __shared__ float ts[32][33];
    int bid = blockIdx.x;
    int tid = threadIdx.x;
    int tx = tid & 31, ty = tid >> 5;

    if (bid < 4096) {
        int z = bid >> 8, rem = bid & 255;
        int m0 = (rem & 31) * 32, c0 = (rem >> 5) * 32;
        bool isq = (z < BB);
        const float* src = isq ? q : v;
        int b = z & (BB - 1);
        const float* sb = src + (size_t)b * CC * NPIX;
        int m = m0 + tx, mi = m >> 5, mj = m & 31;
#pragma unroll
        for (int i = 0; i < 4; i++) {
            int c = c0 + ty + i * 8;
            const float* p = sb + (size_t)c * NPIX + (2 * mi) * WW + 2 * mj;
            ts[ty + i * 8][tx] = 0.25f * (p[0] + p[1] + p[WW] + p[WW + 1]);
        }
        __syncthreads();
        int ch = c0 >> 5;
#pragma unroll
        for (int i = 0; i < 4; i++) {
            float val = ts[tx][ty + i * 8];
            int mm = m0 + ty + i * 8;
            int mtile = mm >> 7, r = mm & 127;
            uint32_t off = lane_off(r, tx);
            __half h = __float2half_rn(val);
            if (isq) {
                char* base = g_pqimg + (size_t)((b * 8 + mtile) * 8 + ch) * 20480;
                *(__half*)(base + off) = h;
                *(__half*)(base + 10240 + off) = __float2half_rn(val - __half2float(h));
            } else {
                *(__half*)(g_pvimg + (size_t)((b * 8 + mtile) * 8 + ch) * 10240 + off) = h;
            }
        }
    } else if (bid < 12288) {
        int i = bid - 4096;
        int b = i >> 10;
        int n0 = (i & 127) * 32, c0 = ((i >> 7) & 7) * 32;
        const float* sb = k + (size_t)b * CC * NPIX;
#pragma unroll
        for (int j = 0; j < 4; j++)
            ts[ty + j * 8][tx] = sb[(size_t)(c0 + ty + j * 8) * NPIX + n0 + tx];
        __syncthreads();
        int ch = c0 >> 5;
#pragma unroll
        for (int j = 0; j < 4; j++) {
            float val = ts[tx][ty + j * 8];
            int nn = n0 + ty + j * 8;
            int nt = nn >> 7, r = nn & 127;
            uint32_t off = lane_off(r, tx);
            char* base = g_kimg + (size_t)((b * 32 + nt) * 8 + ch) * 20480;
            __half h = __float2half_rn(val);
            *(__half*)(base + off) = h;
            *(__half*)(base + 10240 + off) = __float2half_rn(val - __half2float(h));
        }
    } else {
        int i = (bid - 12288) * 256 + tid;
        {
            int row = i >> 8, c = i & 255;
            int ch = c >> 5, cc = c & 31;
            uint32_t off = lane_off(row, cc);
            float a = Wth[i];
            __half h = __float2half_rn(a);
            *(__half*)(g_wthimg + ch * 20480 + off) = h;
            *(__half*)(g_wthimg + ch * 20480 + 10240 + off) = __float2half_rn(a - __half2float(h));
            float p = Wph[i];
            __half hp = __float2half_rn(p);
            *(__half*)(g_wphimg + ch * 20480 + off) = hp;
            *(__half*)(g_wphimg + ch * 20480 + 10240 + off) = __float2half_rn(p - __half2float(hp));
            *(__half*)(g_wgimg + ch * 10240 + off) = __float2half_rn(Wg[i]);
        }
        {
            int row = i >> 7, ci = i & 127;
            int rt = row >> 7, rr = row & 127;
            int ch = ci >> 5, cc = ci & 31;
            *(__half*)(g_wwimg + (rt * 4 + ch) * 10240 + lane_off(rr, cc)) = __float2half_rn(Ww[i]);
        }
        if (i < CC) {
            float sc = gamma[i] * rsqrtf(var[i] + 1e-5f);
            g_bns[i] = sc;
            g_bnt[i] = beta[i] + (bw[i] - mean[i]) * sc;
        }
    }
}

// ---------------- launch ----------------
extern "C" void kernel_launch(void* const* d_in, const int* in_sizes, int n_in,
                              void* d_out, int out_size) {
    (void)in_sizes; (void)n_in; (void)out_size;
    const float* q     = (const float*)d_in[0];
    const float* k     = (const float*)d_in[1];
    const float* v     = (const float*)d_in[2];
    const float* Wg    = (const float*)d_in[3];
    const float* bg    = (const float*)d_in[4];
    const float* Wth   = (const float*)d_in[5];
    const float* bth   = (const float*)d_in[6];
    const float* Wph   = (const float*)d_in[7];
    const float* bph   = (const float*)d_in[8];
    const float* Ww    = (const float*)d_in[9];
    const float* bw    = (const float*)d_in[10];
    const float* gamma = (const float*)d_in[11];
    const float* beta  = (const float*)d_in[12];
    const float* mean  = (const float*)d_in[13];
    const float* var   = (const float*)d_in[14];
    float* out = (float*)d_out;

    const int SMM = 122880;  // mid: 3 x 40960
    const int SMF = 184320;  // flash: 3 x 61440
    cudaFuncSetAttribute(mid_kernel, cudaFuncAttributeMaxDynamicSharedMemorySize, SMM);
    cudaFuncSetAttribute(flash_kernel, cudaFuncAttributeMaxDynamicSharedMemorySize, SMF);

    // 1) merged prep -> images
    prep_kernel<<<12416, 256>>>(q, v, k, Wth, Wph, Wg, Ww, gamma, beta, mean, var, bw);
    // 2) phi + g projections
    mid_kernel<<<128, 256, SMM>>>(bph, bg);
    // 3) fused flash: theta + attention + final GEMM + BN + residual
    flash_kernel<<<dim3(NPIX / 128, BB), 256, SMF>>>(bth, v, out);
}

// round 16
// speedup vs baseline: 1.0332x; 1.0194x over previous
#include <cuda_runtime.h>
#include <cuda_fp16.h>
#include <cstdint>
#include <cstddef>

// Problem dims
#define BB   8
#define CC   256
#define CHI  128
#define HH   64
#define WW   64
#define NPIX 4096   // H*W
#define MPOOL 1024  // (H/2)*(W/2)

// ---------------- gmem "smem-image" buffers ----------------
// lane_off(r, c<32) = r*80 + (c>>3)*16 + (c&7)*2
__device__ __align__(128) char g_kimg[(size_t)8 * 32 * 8 * 20480];
__device__ __align__(128) char g_wthimg[8 * 20480];
__device__ __align__(128) char g_wphimg[8 * 20480];
__device__ __align__(128) char g_wgimg[8 * 10240];
__device__ __align__(128) char g_wwimg[8 * 10240];
__device__ __align__(128) char g_pqimg[(size_t)8 * 8 * 8 * 20480];
__device__ __align__(128) char g_pvimg[(size_t)8 * 8 * 8 * 10240];
// pgimg: per (b, mt64) 61440 = [phi_hi 4ch x 64x80 | phi_lo | g 2ch x 128x80]
__device__ __align__(128) char g_pgimg[(size_t)8 * 16 * 61440];
__device__ float g_bns[CC];
__device__ float g_bnt[CC];

// ---------------- PTX helpers ----------------
__device__ __forceinline__ uint32_t smem_u32(const void* p) {
    uint32_t a;
    asm("{ .reg .u64 t; cvta.to.shared.u64 t, %1; cvt.u32.u64 %0, t; }" : "=r"(a) : "l"(p));
    return a;
}
__device__ __forceinline__ void cpbulk(uint32_t dst, const void* src, uint32_t bytes,
                                       uint32_t mbar) {
    asm volatile(
        "cp.async.bulk.shared::cluster.global.mbarrier::complete_tx::bytes [%0], [%1], %2, [%3];"
        :: "r"(dst), "l"(src), "r"(bytes), "r"(mbar) : "memory");
}
#define MBAR_INIT(mb, n) \
    asm volatile("mbarrier.init.shared.b64 [%0], %1;" :: "r"(mb), "r"((uint32_t)(n)) : "memory")
#define MBAR_EXPECT(mb, n) \
    asm volatile("mbarrier.arrive.expect_tx.shared.b64 _, [%0], %1;" :: "r"(mb), "r"((uint32_t)(n)) : "memory")

__device__ __forceinline__ void mbar_wait(uint32_t mb, uint32_t parity) {
    uint32_t done;
    asm volatile(
        "{\n\t.reg .pred p;\n\t"
        "mbarrier.try_wait.parity.acquire.cta.shared::cta.b64 p, [%1], %2;\n\t"
        "selp.b32 %0, 1, 0, p;\n\t}"
        : "=r"(done) : "r"(mb), "r"(parity) : "memory");
    if (!done) {
        asm volatile(
            "{\n\t.reg .pred P1;\n\t"
            "W0_%=:\n\t"
            "mbarrier.try_wait.parity.acquire.cta.shared::cta.b64 P1, [%0], %1, 0x989680;\n\t"
            "@P1 bra.uni W1_%=;\n\t"
            "bra.uni W0_%=;\n\t"
            "W1_%=:\n\t}"
            :: "r"(mb), "r"(parity) : "memory");
    }
}
__device__ __forceinline__ void ldsm4(uint32_t& r0, uint32_t& r1, uint32_t& r2, uint32_t& r3,
                                      uint32_t a) {
    asm volatile("ldmatrix.sync.aligned.m8n8.x4.shared.b16 {%0,%1,%2,%3}, [%4];"
                 : "=r"(r0), "=r"(r1), "=r"(r2), "=r"(r3) : "r"(a));
}
__device__ __forceinline__ void mma16816(float* c, const uint32_t* a, const uint32_t* b) {
    asm volatile(
        "mma.sync.aligned.m16n8k16.row.col.f32.f16.f16.f32 "
        "{%0,%1,%2,%3}, {%4,%5,%6,%7}, {%8,%9}, {%0,%1,%2,%3};"
        : "+f"(c[0]), "+f"(c[1]), "+f"(c[2]), "+f"(c[3])
        : "r"(a[0]), "r"(a[1]), "r"(a[2]), "r"(a[3]), "r"(b[0]), "r"(b[1]));
}
__device__ __forceinline__ uint32_t pkh2(float a, float b) {
    __half2 h = __floats2half2_rn(a, b);
    return *(uint32_t*)&h;
}
__device__ __forceinline__ uint32_t lane_off(int r, int c) {
    return (uint32_t)(r * 80 + (c >> 3) * 16 + (c & 7) * 2);
}

// ---------------- 3-stage bulk-fed GEMM body (phi/g projections) ----------------
// EPI 5: phi -> pgimg (col bias, split hi/lo) | 6: g -> pgimg (row bias)
template <int NCH, bool SPLIT, int EPI>
__device__ __forceinline__ void gemm_body(
    const char* __restrict__ Ab, const char* __restrict__ Bb,
    char* smraw, uint32_t mb0, int z, int by, int bx,
    const float* __restrict__ bias, char* __restrict__ outImg, int tid) {
    constexpr uint32_t REG = SPLIT ? 20480 : 10240;
    constexpr uint32_t STAGE = SPLIT ? 40960 : 20480;
    uint32_t sbase = smem_u32(smraw);
    int lane = tid & 31, w = tid >> 5;
    int wm = w >> 2, wn = w & 3;

    if (tid == 0) { MBAR_INIT(mb0, 1); MBAR_INIT(mb0 + 8, 1); MBAR_INIT(mb0 + 16, 1); }
    __syncthreads();

    auto issue = [&](int ch) {
        uint32_t st = sbase + (uint32_t)(ch % 3) * STAGE;
        uint32_t mb = mb0 + (uint32_t)(ch % 3) * 8;
        MBAR_EXPECT(mb, SPLIT ? 40960u : 20480u);
        if (SPLIT) {
            cpbulk(st, Ab + (size_t)ch * REG, 10240, mb);
            cpbulk(st + 20480, Ab + (size_t)ch * REG + 10240, 10240, mb);
            cpbulk(st + 10240, Bb + (size_t)ch * REG, 10240, mb);
            cpbulk(st + 30720, Bb + (size_t)ch * REG + 10240, 10240, mb);
        } else {
            cpbulk(st, Ab + (size_t)ch * REG, 10240, mb);
            cpbulk(st + 10240, Bb + (size_t)ch * REG, 10240, mb);
        }
    };
    if (tid == 0) { issue(0); issue(1); issue(2); }

    float acc[4][4][4];
#pragma unroll
    for (int i = 0; i < 4; i++)
#pragma unroll
        for (int j = 0; j < 4; j++)
#pragma unroll
            for (int e = 0; e < 4; e++) acc[i][j][e] = 0.f;

    for (int ch = 0; ch < NCH; ch++) {
        mbar_wait(mb0 + (uint32_t)(ch % 3) * 8, (uint32_t)((ch / 3) & 1));
        uint32_t sa = sbase + (uint32_t)(ch % 3) * STAGE;
        uint32_t sb = sa + 10240;
#pragma unroll
        for (int k16 = 0; k16 < 2; k16++) {
            uint32_t a[4][4], b[4][2];
            uint32_t coff = (uint32_t)(k16 * 32 + (lane >> 4) * 16);
#pragma unroll
            for (int mi = 0; mi < 4; mi++) {
                uint32_t ad = sa + (uint32_t)(wm * 64 + mi * 16 + (lane & 15)) * 80 + coff;
                ldsm4(a[mi][0], a[mi][1], a[mi][2], a[mi][3], ad);
            }
#pragma unroll
            for (int nh = 0; nh < 2; nh++) {
                uint32_t bd = sb + (uint32_t)(wn * 32 + nh * 16 + (lane & 15)) * 80 + coff;
                uint32_t r0, r1, r2, r3;
                ldsm4(r0, r1, r2, r3, bd);
                b[nh * 2 + 0][0] = r0; b[nh * 2 + 0][1] = r2;
                b[nh * 2 + 1][0] = r1; b[nh * 2 + 1][1] = r3;
            }
#pragma unroll
            for (int mi = 0; mi < 4; mi++)
#pragma unroll
                for (int ni = 0; ni < 4; ni++) mma16816(acc[mi][ni], a[mi], b[ni]);
            if (SPLIT) {
                uint32_t al[4][4], bl[4][2];
#pragma unroll
                for (int mi = 0; mi < 4; mi++) {
                    uint32_t ad = sa + 20480 + (uint32_t)(wm * 64 + mi * 16 + (lane & 15)) * 80 + coff;
                    ldsm4(al[mi][0], al[mi][1], al[mi][2], al[mi][3], ad);
                }
#pragma unroll
                for (int nh = 0; nh < 2; nh++) {
                    uint32_t bd = sa + 30720 + (uint32_t)(wn * 32 + nh * 16 + (lane & 15)) * 80 + coff;
                    uint32_t r0, r1, r2, r3;
                    ldsm4(r0, r1, r2, r3, bd);
                    bl[nh * 2 + 0][0] = r0; bl[nh * 2 + 0][1] = r2;
                    bl[nh * 2 + 1][0] = r1; bl[nh * 2 + 1][1] = r3;
                }
#pragma unroll
                for (int mi = 0; mi < 4; mi++)
#pragma unroll
                    for (int ni = 0; ni < 4; ni++) {
                        mma16816(acc[mi][ni], a[mi], bl[ni]);
                        mma16816(acc[mi][ni], al[mi], b[ni]);
                    }
            }
        }
        __syncthreads();
        if (tid == 0 && ch + 3 < NCH) issue(ch + 3);
    }

    int r = lane >> 2, cp2 = (lane & 3) * 2;
    int row0 = by * 128 + wm * 64;
    int col0 = bx * 128 + wn * 32;
#pragma unroll
    for (int mi = 0; mi < 4; mi++) {
#pragma unroll
        for (int h = 0; h < 2; h++) {
            int row = row0 + mi * 16 + h * 8 + r;
            float t = (EPI == 6) ? bias[row] : 0.f;
#pragma unroll
            for (int ni = 0; ni < 4; ni++) {
                int col = col0 + ni * 8 + cp2;
                float v0 = acc[mi][ni][h * 2 + 0];
                float v1 = acc[mi][ni][h * 2 + 1];
                if (EPI == 5) {
                    v0 += bias[col]; v1 += bias[col + 1];
                    __half h0 = __float2half_rn(v0), h1 = __float2half_rn(v1);
                    uint32_t hi = ((uint32_t)*(uint16_t*)&h1 << 16) | *(uint16_t*)&h0;
                    uint32_t lo = pkh2(v0 - __half2float(h0), v1 - __half2float(h1));
                    char* base = outImg + (size_t)(z * 16 + (row >> 6)) * 61440;
                    uint32_t off = (uint32_t)(col >> 5) * 5120 + lane_off(row & 63, col & 31);
                    *(uint32_t*)(base + off) = hi;
                    *(uint32_t*)(base + off + 20480) = lo;
                } else {
                    uint32_t hv = pkh2(v0 + t, v1 + t);
                    char* base = outImg + (size_t)(z * 16 + (col >> 6)) * 61440 + 40960;
                    uint32_t off = (uint32_t)((col >> 5) & 1) * 10240 + lane_off(row, col & 31);
                    *(uint32_t*)(base + off) = hv;
                }
            }
        }
    }
}

// ---------------- mid kernel: phi (blocks 0-63) + g (blocks 64-127) ----------------
__global__ void __launch_bounds__(256, 1) mid_kernel(const float* __restrict__ bph,
                                                     const float* __restrict__ bg) {
    extern __shared__ char sm[];
    __shared__ __align__(8) uint64_t s_mbar[3];
    int tid = threadIdx.x;
    uint32_t mb0 = smem_u32(&s_mbar[0]);
    if (blockIdx.x < 64) {
        int z = blockIdx.x >> 3, by = blockIdx.x & 7;
        const char* Ab = g_pqimg + (size_t)(z * 8 + by) * (8 * 20480);
        gemm_body<8, true, 5>(Ab, g_wphimg, sm, mb0, z, by, 0, bph, g_pgimg, tid);
    } else {
        int i = blockIdx.x - 64;
        int z = i >> 3, bx = i & 7;
        const char* Bb = g_pvimg + (size_t)(z * 8 + bx) * (8 * 10240);
        gemm_body<8, false, 6>(g_wgimg, Bb, sm, mb0, z, 0, bx, bg, g_pgimg, tid);
    }
}

// ---------------- fused flash: theta prologue + S-softmax-y + final Ww GEMM + BN + resid ----------------
__global__ void __launch_bounds__(256, 1) flash_kernel(const float* __restrict__ bth,
                                                       const float* __restrict__ vres,
                                                       float* __restrict__ out) {
    extern __shared__ char sm[];
    __shared__ __align__(8) uint64_t s_mbar[3];
    uint32_t sbase = smem_u32(sm);
    uint32_t mb0 = smem_u32(&s_mbar[0]);
    const uint32_t STGSZ = 61440;

    int tid = threadIdx.x, lane = tid & 31, w = tid >> 5;
    int b = blockIdx.y;
    int nt = blockIdx.x;
    const char* kimgT = g_kimg + (size_t)(b * 32 + nt) * 8 * 20480;
    const char* pgB = g_pgimg + (size_t)b * 16 * 61440;

    if (tid == 0) { MBAR_INIT(mb0, 1); MBAR_INIT(mb0 + 8, 1); MBAR_INIT(mb0 + 16, 1); }
    __syncthreads();

    // chunk counter t: 0..7 prologue (k+Wth), 8..23 main (phi+g)
    auto issue = [&](int t) {
        uint32_t st = sbase + (uint32_t)(t % 3) * STGSZ;
        uint32_t mb = mb0 + (uint32_t)(t % 3) * 8;
        if (t < 8) {
            MBAR_EXPECT(mb, 40960u);
            cpbulk(st, kimgT + (size_t)t * 20480, 20480, mb);
            cpbulk(st + 20480, g_wthimg + (size_t)t * 20480, 20480, mb);
        } else {
            MBAR_EXPECT(mb, 61440u);
            cpbulk(st, pgB + (size_t)(t - 8) * 61440, 61440, mb);
        }
    };
    if (tid == 0) { issue(0); issue(1); issue(2); }

    // ======== PROLOGUE: theta = kT.Wth^T (3-pass split, 4-acc interleave) ========
    float acc[16][4];
#pragma unroll
    for (int j = 0; j < 16; j++)
#pragma unroll
        for (int e = 0; e < 4; e++) acc[j][e] = 0.f;

    for (int ch = 0; ch < 8; ch++) {
        mbar_wait(mb0 + (uint32_t)(ch % 3) * 8, (uint32_t)((ch / 3) & 1));
        uint32_t st = sbase + (uint32_t)(ch % 3) * STGSZ;
#pragma unroll
        for (int k16 = 0; k16 < 2; k16++) {
            uint32_t coff = (uint32_t)(k16 * 32 + (lane >> 4) * 16);
            uint32_t arow = (uint32_t)(w * 16 + (lane & 15)) * 80;
            uint32_t ah[4], al[4];
            ldsm4(ah[0], ah[1], ah[2], ah[3], st + arow + coff);
            ldsm4(al[0], al[1], al[2], al[3], st + 10240 + arow + coff);
#pragma unroll
            for (int np = 0; np < 4; np++) {  // nh pairs (2np, 2np+1)
                uint32_t bh[2][2][2], bl[2][2][2];
#pragma unroll
                for (int i = 0; i < 2; i++) {
                    int nh = 2 * np + i;
                    uint32_t brow = (uint32_t)(nh * 16 + (lane & 15)) * 80;
                    uint32_t r0, r1, r2, r3;
                    ldsm4(r0, r1, r2, r3, st + 20480 + brow + coff);
                    bh[i][0][0] = r0; bh[i][0][1] = r2; bh[i][1][0] = r1; bh[i][1][1] = r3;
                    ldsm4(r0, r1, r2, r3, st + 30720 + brow + coff);
                    bl[i][0][0] = r0; bl[i][0][1] = r2; bl[i][1][0] = r1; bl[i][1][1] = r3;
                }
                // pass-major: per-acc sequence stays (ah*bh, ah*bl, al*bh)
#pragma unroll
                for (int i = 0; i < 2; i++) {
                    int nh = 2 * np + i;
                    mma16816(acc[2 * nh], ah, bh[i][0]);
                    mma16816(acc[2 * nh + 1], ah, bh[i][1]);
                }
#pragma unroll
                for (int i = 0; i < 2; i++) {
                    int nh = 2 * np + i;
                    mma16816(acc[2 * nh], ah, bl[i][0]);
                    mma16816(acc[2 * nh + 1], ah, bl[i][1]);
                }
#pragma unroll
                for (int i = 0; i < 2; i++) {
                    int nh = 2 * np + i;
                    mma16816(acc[2 * nh], al, bh[i][0]);
                    mma16816(acc[2 * nh + 1], al, bh[i][1]);
                }
            }
        }
        __syncthreads();
        if (tid == 0) issue(ch + 3);
    }

    // bias + hi/lo split -> A-fragments
    uint32_t th_hi[8][4], th_lo[8][4];
    {
        int t2 = (lane & 3) * 2;
#pragma unroll
        for (int s = 0; s < 8; s++) {
#pragma unroll
            for (int hf = 0; hf < 2; hf++) {
                int nb = 2 * s + hf;
                float b0 = bth[8 * nb + t2], b1 = bth[8 * nb + t2 + 1];
                float x0 = acc[nb][0] + b0, x1 = acc[nb][1] + b1;
                float x2 = acc[nb][2] + b0, x3 = acc[nb][3] + b1;
                __half hx0 = __float2half_rn(x0), hx1 = __float2half_rn(x1);
                __half hx2 = __float2half_rn(x2), hx3 = __float2half_rn(x3);
                th_hi[s][2 * hf + 0] = ((uint32_t)*(uint16_t*)&hx1 << 16) | *(uint16_t*)&hx0;
                th_hi[s][2 * hf + 1] = ((uint32_t)*(uint16_t*)&hx3 << 16) | *(uint16_t*)&hx2;
                th_lo[s][2 * hf + 0] = pkh2(x0 - __half2float(hx0), x1 - __half2float(hx1));
                th_lo[s][2 * hf + 1] = pkh2(x2 - __half2float(hx2), x3 - __half2float(hx3));
            }
        }
    }

    // ======== MAIN LOOP: S -> online softmax -> y ========
    float yacc[16][4];
#pragma unroll
    for (int j = 0; j < 16; j++)
#pragma unroll
        for (int e = 0; e < 4; e++) yacc[j][e] = 0.f;
    float rmax0 = -1e30f, rmax1 = -1e30f, rsum0 = 0.f, rsum1 = 0.f;

    for (int mt = 0; mt < 16; mt++) {
        int t = 8 + mt;
        mbar_wait(mb0 + (uint32_t)(t % 3) * 8, (uint32_t)((t / 3) & 1));
        uint32_t st = sbase + (uint32_t)(t % 3) * STGSZ;

        float sacc[8][4];
#pragma unroll
        for (int j = 0; j < 8; j++)
#pragma unroll
            for (int e = 0; e < 4; e++) sacc[j][e] = 0.f;

#pragma unroll
        for (int s = 0; s < 8; s++) {
            uint32_t chunk = (uint32_t)(s >> 1);
            uint32_t inner = (uint32_t)((s & 1) * 32 + (lane >> 4) * 16);
#pragma unroll
            for (int pp = 0; pp < 2; pp++) {  // p pairs (2pp, 2pp+1)
                uint32_t bh[2][2][2], bl[2][2][2];
#pragma unroll
                for (int pi = 0; pi < 2; pi++) {
                    int p = 2 * pp + pi;
                    uint32_t brow = (uint32_t)(p * 16 + (lane & 15)) * 80;
                    uint32_t bad = st + chunk * 5120 + brow + inner;
                    uint32_t r0, r1, r2, r3;
                    ldsm4(r0, r1, r2, r3, bad);
                    bh[pi][0][0] = r0; bh[pi][0][1] = r2; bh[pi][1][0] = r1; bh[pi][1][1] = r3;
                    ldsm4(r0, r1, r2, r3, bad + 20480);
                    bl[pi][0][0] = r0; bl[pi][0][1] = r2; bl[pi][1][0] = r1; bl[pi][1][1] = r3;
                }
                // pass-major: per-acc sequence stays (th_hi*bh, th_hi*bl, th_lo*bh)
#pragma unroll
                for (int pi = 0; pi < 2; pi++) {
                    int p = 2 * pp + pi;
                    mma16816(sacc[2 * p], th_hi[s], bh[pi][0]);
                    mma16816(sacc[2 * p + 1], th_hi[s], bh[pi][1]);
                }
#pragma unroll
                for (int pi = 0; pi < 2; pi++) {
                    int p = 2 * pp + pi;
                    mma16816(sacc[2 * p], th_hi[s], bl[pi][0]);
                    mma16816(sacc[2 * p + 1], th_hi[s], bl[pi][1]);
                }
#pragma unroll
                for (int pi = 0; pi < 2; pi++) {
                    int p = 2 * pp + pi;
                    mma16816(sacc[2 * p], th_lo[s], bh[pi][0]);
                    mma16816(sacc[2 * p + 1], th_lo[s], bh[pi][1]);
                }
            }
        }

        // ---- online softmax ----
        float tm0 = -1e30f, tm1 = -1e30f;
#pragma unroll
        for (int j = 0; j < 8; j++) {
            tm0 = fmaxf(tm0, fmaxf(sacc[j][0], sacc[j][1]));
            tm1 = fmaxf(tm1, fmaxf(sacc[j][2], sacc[j][3]));
        }
        tm0 = fmaxf(tm0, __shfl_xor_sync(0xffffffffu, tm0, 1));
        tm0 = fmaxf(tm0, __shfl_xor_sync(0xffffffffu, tm0, 2));
        tm1 = fmaxf(tm1, __shfl_xor_sync(0xffffffffu, tm1, 1));
        tm1 = fmaxf(tm1, __shfl_xor_sync(0xffffffffu, tm1, 2));
        float mn0 = fmaxf(rmax0, tm0), mn1 = fmaxf(rmax1, tm1);
        float sc0 = __expf(rmax0 - mn0), sc1 = __expf(rmax1 - mn1);
        float ts0 = 0.f, ts1 = 0.f;
#pragma unroll
        for (int j = 0; j < 8; j++) {
            sacc[j][0] = __expf(sacc[j][0] - mn0);
            sacc[j][1] = __expf(sacc[j][1] - mn0);
            sacc[j][2] = __expf(sacc[j][2] - mn1);
            sacc[j][3] = __expf(sacc[j][3] - mn1);
            ts0 += sacc[j][0] + sacc[j][1];
            ts1 += sacc[j][2] + sacc[j][3];
        }
        ts0 += __shfl_xor_sync(0xffffffffu, ts0, 1);
        ts0 += __shfl_xor_sync(0xffffffffu, ts0, 2);
        ts1 += __shfl_xor_sync(0xffffffffu, ts1, 1);
        ts1 += __shfl_xor_sync(0xffffffffu, ts1, 2);
        rsum0 = rsum0 * sc0 + ts0;
        rsum1 = rsum1 * sc1 + ts1;
        rmax0 = mn0; rmax1 = mn1;
#pragma unroll
        for (int j = 0; j < 16; j++) {
            yacc[j][0] *= sc0; yacc[j][1] *= sc0;
            yacc[j][2] *= sc1; yacc[j][3] *= sc1;
        }

        uint32_t pf[4][4];
#pragma unroll
        for (int s2 = 0; s2 < 4; s2++) {
            pf[s2][0] = pkh2(sacc[2 * s2][0], sacc[2 * s2][1]);
            pf[s2][1] = pkh2(sacc[2 * s2][2], sacc[2 * s2][3]);
            pf[s2][2] = pkh2(sacc[2 * s2 + 1][0], sacc[2 * s2 + 1][1]);
            pf[s2][3] = pkh2(sacc[2 * s2 + 1][2], sacc[2 * s2 + 1][3]);
        }

#pragma unroll
        for (int s2 = 0; s2 < 4; s2++) {
            uint32_t chunk = (uint32_t)(s2 >> 1);
            uint32_t inner = (uint32_t)((s2 & 1) * 32 + (lane >> 4) * 16);
#pragma unroll
            for (int pc = 0; pc < 8; pc++) {
                uint32_t brow = (uint32_t)(pc * 16 + (lane & 15)) * 80;
                uint32_t r0, r1, r2, r3;
                ldsm4(r0, r1, r2, r3, st + 40960 + chunk * 10240 + brow + inner);
                uint32_t bb0[2] = {r0, r2};
                uint32_t bb1[2] = {r1, r3};
                mma16816(yacc[2 * pc], pf[s2], bb0);
                mma16816(yacc[2 * pc + 1], pf[s2], bb1);
            }
        }
        __syncthreads();
        if (tid == 0 && t + 3 < 24) issue(t + 3);
    }

    // ======== EPILOGUE: pack y into B-frags, out = BN(Ww.y^T) + v ========
    float inv0 = 1.f / rsum0, inv1 = 1.f / rsum1;
    uint32_t yB[8][2][2];
#pragma unroll
    for (int s = 0; s < 8; s++) {
        yB[s][0][0] = pkh2(yacc[2 * s][0] * inv0, yacc[2 * s][1] * inv0);
        yB[s][0][1] = pkh2(yacc[2 * s + 1][0] * inv0, yacc[2 * s + 1][1] * inv0);
        yB[s][1][0] = pkh2(yacc[2 * s][2] * inv1, yacc[2 * s][3] * inv1);
        yB[s][1][1] = pkh2(yacc[2 * s + 1][2] * inv1, yacc[2 * s + 1][3] * inv1);
    }

    // pull full Ww image (80KB) into stage smem (slot0, 9th completion -> parity 0)
    if (tid == 0) {
        MBAR_EXPECT(mb0, 81920u);
        cpbulk(sbase, g_wwimg, 81920, mb0);
    }
    mbar_wait(mb0, 0u);

    int r = lane >> 2, c2 = (lane & 3) * 2;
    int nbase = nt * 128 + w * 16;
#pragma unroll
    for (int coh = 0; coh < 2; coh++) {
        float oacc[8][2][4];
#pragma unroll
        for (int ct = 0; ct < 8; ct++)
#pragma unroll
            for (int nf = 0; nf < 2; nf++)
#pragma unroll
                for (int e = 0; e < 4; e++) oacc[ct][nf][e] = 0.f;

#pragma unroll
        for (int s = 0; s < 8; s++) {
            uint32_t coff = (uint32_t)((s & 1) * 32 + (lane >> 4) * 16);
            uint32_t rbase = sbase + (uint32_t)(coh * 4 + (s >> 1)) * 10240;
#pragma unroll
            for (int ct = 0; ct < 8; ct++) {
                uint32_t a[4];
                ldsm4(a[0], a[1], a[2], a[3],
                      rbase + (uint32_t)(ct * 16 + (lane & 15)) * 80 + coff);
                mma16816(oacc[ct][0], a, yB[s][0]);
                mma16816(oacc[ct][1], a, yB[s][1]);
            }
        }

#pragma unroll
        for (int ct = 0; ct < 8; ct++) {
#pragma unroll
            for (int h = 0; h < 2; h++) {
                int co = coh * 128 + ct * 16 + h * 8 + r;
                float s1 = g_bns[co], t1 = g_bnt[co];
                size_t rowb = (size_t)b * CC * NPIX + (size_t)co * NPIX;
#pragma unroll
                for (int nf = 0; nf < 2; nf++) {
                    int n = nbase + nf * 8 + c2;
                    float2 rr = *(const float2*)(vres + rowb + n);
                    float v0 = oacc[ct][nf][h * 2 + 0] * s1 + t1 + rr.x;
                    float v1 = oacc[ct][nf][h * 2 + 1] * s1 + t1 + rr.y;
                    *(float2*)(out + rowb + n) = make_float2(v0, v1);
                }
            }
        }
    }
}

// ---------------- merged prep: pooltrans (0..4095) + transk (4096..12287) + wprep ----------------
__global__ void __launch_bounds__(256) prep_kernel(
    const float* __restrict__ q, const float* __restrict__ v, const float* __restrict__ k,
    const float* __restrict__ Wth, const float* __restrict__ Wph,
    const float* __restrict__ Wg, const float* __restrict__ Ww,
    const float* __restrict__ gamma, const float* __restrict__ beta,
    const float* __restrict__ mean, const float* __restrict__ var,
    const float* __restrict__ bw) {
    __shared__ float ts[32][33];
    int bid = blockIdx.x;
    int tid = threadIdx.x;
    int tx = tid & 31, ty = tid >> 5;

    if (bid < 4096) {
        int z = bid >> 8, rem = bid & 255;
        int m0 = (rem & 31) * 32, c0 = (rem >> 5) * 32;
        bool isq = (z < BB);
        const float* src = isq ? q : v;
        int b = z & (BB - 1);
        const float* sb = src + (size_t)b * CC * NPIX;
        int m = m0 + tx, mi = m >> 5, mj = m & 31;
#pragma unroll
        for (int i = 0; i < 4; i++) {
            int c = c0 + ty + i * 8;
            const float* p = sb + (size_t)c * NPIX + (2 * mi) * WW + 2 * mj;
            ts[ty + i * 8][tx] = 0.25f * (p[0] + p[1] + p[WW] + p[WW + 1]);
        }
        __syncthreads();
        int ch = c0 >> 5;
#pragma unroll
        for (int i = 0; i < 4; i++) {
            float val = ts[tx][ty + i * 8];
            int mm = m0 + ty + i * 8;
            int mtile = mm >> 7, r = mm & 127;
            uint32_t off = lane_off(r, tx);
            __half h = __float2half_rn(val);
            if (isq) {
                char* base = g_pqimg + (size_t)((b * 8 + mtile) * 8 + ch) * 20480;
                *(__half*)(base + off) = h;
                *(__half*)(base + 10240 + off) = __float2half_rn(val - __half2float(h));
            } else {
                *(__half*)(g_pvimg + (size_t)((b * 8 + mtile) * 8 + ch) * 10240 + off) = h;
            }
        }
    } else if (bid < 12288) {
        int i = bid - 4096;
        int b = i >> 10;
        int n0 = (i & 127) * 32, c0 = ((i >> 7) & 7) * 32;
        const float* sb = k + (size_t)b * CC * NPIX;
#pragma unroll
        for (int j = 0; j < 4; j++)
            ts[ty + j * 8][tx] = sb[(size_t)(c0 + ty + j * 8) * NPIX + n0 + tx];
        __syncthreads();
        int ch = c0 >> 5;
#pragma unroll
        for (int j = 0; j < 4; j++) {
            float val = ts[tx][ty + j * 8];
            int nn = n0 + ty + j * 8;
            int nt = nn >> 7, r = nn & 127;
            uint32_t off = lane_off(r, tx);
            char* base = g_kimg + (size_t)((b * 32 + nt) * 8 + ch) * 20480;
            __half h = __float2half_rn(val);
            *(__half*)(base + off) = h;
            *(__half*)(base + 10240 + off) = __float2half_rn(val - __half2float(h));
        }
    } else {
        int i = (bid - 12288) * 256 + tid;
        {
            int row = i >> 8, c = i & 255;
            int ch = c >> 5, cc = c & 31;
            uint32_t off = lane_off(row, cc);
            float a = Wth[i];
            __half h = __float2half_rn(a);
            *(__half*)(g_wthimg + ch * 20480 + off) = h;
            *(__half*)(g_wthimg + ch * 20480 + 10240 + off) = __float2half_rn(a - __half2float(h));
            float p = Wph[i];
            __half hp = __float2half_rn(p);
            *(__half*)(g_wphimg + ch * 20480 + off) = hp;
            *(__half*)(g_wphimg + ch * 20480 + 10240 + off) = __float2half_rn(p - __half2float(hp));
            *(__half*)(g_wgimg + ch * 10240 + off) = __float2half_rn(Wg[i]);
        }
        {
            int row = i >> 7, ci = i & 127;
            int rt = row >> 7, rr = row & 127;
            int ch = ci >> 5, cc = ci & 31;
            *(__half*)(g_wwimg + (rt * 4 + ch) * 10240 + lane_off(rr, cc)) = __float2half_rn(Ww[i]);
        }
        if (i < CC) {
            float sc = gamma[i] * rsqrtf(var[i] + 1e-5f);
            g_bns[i] = sc;
            g_bnt[i] = beta[i] + (bw[i] - mean[i]) * sc;
        }
    }
}

// ---------------- launch ----------------
extern "C" void kernel_launch(void* const* d_in, const int* in_sizes, int n_in,
                              void* d_out, int out_size) {
    (void)in_sizes; (void)n_in; (void)out_size;
    const float* q     = (const float*)d_in[0];
    const float* k     = (const float*)d_in[1];
    const float* v     = (const float*)d_in[2];
    const float* Wg    = (const float*)d_in[3];
    const float* bg    = (const float*)d_in[4];
    const float* Wth   = (const float*)d_in[5];
    const float* bth   = (const float*)d_in[6];
    const float* Wph   = (const float*)d_in[7];
    const float* bph   = (const float*)d_in[8];
    const float* Ww    = (const float*)d_in[9];
    const float* bw    = (const float*)d_in[10];
    const float* gamma = (const float*)d_in[11];
    const float* beta  = (const float*)d_in[12];
    const float* mean  = (const float*)d_in[13];
    const float* var   = (const float*)d_in[14];
    float* out = (float*)d_out;

    const int SMM = 122880;  // mid: 3 x 40960
    const int SMF = 184320;  // flash: 3 x 61440
    cudaFuncSetAttribute(mid_kernel, cudaFuncAttributeMaxDynamicSharedMemorySize, SMM);
    cudaFuncSetAttribute(flash_kernel, cudaFuncAttributeMaxDynamicSharedMemorySize, SMF);

    // 1) merged prep -> images
    prep_kernel<<<12416, 256>>>(q, v, k, Wth, Wph, Wg, Ww, gamma, beta, mean, var, bw);
    // 2) phi + g projections
    mid_kernel<<<128, 256, SMM>>>(bph, bg);
    // 3) fused flash: theta + attention + final GEMM + BN + residual
    flash_kernel<<<dim3(NPIX / 128, BB), 256, SMF>>>(bth, v, out);
}